// round 11
// baseline (speedup 1.0000x reference)
#include <cuda_runtime.h>
#include <cstdint>

#define SZ 512
#define SLAB 128
#define NPLANES 256

#define STG_WARP   6144      // 3 stages x 4 rows x 512 B per warp
#define STAGE_B    2048
#define OFF_COLP   98304     // sColPart[4][512]
#define OFF_BAND   106496    // sBandRow[4][128]
#define OFF_CUTM   108544
#define OFF_CUTA   109056
#define OFF_SNM    109568
#define OFF_SNA    110080
#define OFF_DAE    110592
#define SMEM_TOTAL 111104

// cross-block scratch (allocation-free: __device__ globals)
__device__ float g_colsum[NPLANES][4][SZ];
__device__ float g_snapM[NPLANES][SZ];
__device__ float g_snapA[NPLANES][SZ];
__device__ float g_RT[NPLANES][SZ];
__device__ float g_PM[NPLANES][SZ];
__device__ float g_PA[NPLANES][SZ];
__device__ float g_DA[NPLANES][SZ];
__device__ unsigned int g_cnt[NPLANES];

__device__ __forceinline__ uint64_t pack2(float lo, float hi) {
    uint64_t d; asm("mov.b64 %0, {%1, %2};" : "=l"(d) : "f"(lo), "f"(hi)); return d;
}
__device__ __forceinline__ void unpack2(uint64_t d, float& lo, float& hi) {
    asm("mov.b64 {%0, %1}, %2;" : "=f"(lo), "=f"(hi) : "l"(d));
}
__device__ __forceinline__ uint64_t addf32x2(uint64_t a, uint64_t b) {
    uint64_t d; asm("add.rn.f32x2 %0, %1, %2;" : "=l"(d) : "l"(a), "l"(b)); return d;
}
__device__ __forceinline__ void cpasync16(uint32_t dst, const float* src) {
    asm volatile("cp.async.cg.shared.global [%0], [%1], 16;" :: "r"(dst), "l"(src));
}
#define CP_COMMIT()  asm volatile("cp.async.commit_group;")
#define CP_WAIT(N)   asm volatile("cp.async.wait_group %0;" :: "n"(N))

// Reduce 4 independent per-lane values over the warp in 6 shuffles.
// Lane L ends holding the full 32-lane sum of value (L & 3).
__device__ __forceinline__ float multireduce4(float v0, float v1, float v2, float v3, int lane) {
    const unsigned F = 0xffffffffu;
    const bool b0 = lane & 1;
    float x01 = (b0 ? v1 : v0) + __shfl_xor_sync(F, b0 ? v0 : v1, 1);
    float x23 = (b0 ? v3 : v2) + __shfl_xor_sync(F, b0 ? v2 : v3, 1);
    const bool b1 = lane & 2;
    float y = (b1 ? x23 : x01) + __shfl_xor_sync(F, b1 ? x01 : x23, 2);
    y += __shfl_xor_sync(F, y, 4);
    y += __shfl_xor_sync(F, y, 8);
    y += __shfl_xor_sync(F, y, 16);
    return y;
}

__global__ __launch_bounds__(512, 2)
void slab_kernel(const float* __restrict__ x, float* __restrict__ out) {
    extern __shared__ char SB[];
    float* sColPart = (float*)(SB + OFF_COLP);   // [band][512]
    float* sBandRow = (float*)(SB + OFF_BAND);   // [band][128]
    float* sCutM    = (float*)(SB + OFF_CUTM);
    float* sCutA    = (float*)(SB + OFF_CUTA);
    float* sSnapM   = (float*)(SB + OFF_SNM);
    float* sSnapA   = (float*)(SB + OFF_SNA);
    float* sDA      = (float*)(SB + OFF_DAE);
    // last-block combine arrays alias the (dead) staging region
    float* cA1  = (float*)(SB + 0);
    float* cA2  = (float*)(SB + 2048);
    float* cCT  = (float*)(SB + 4096);
    float* cRT  = (float*)(SB + 6144);
    float* cPM  = (float*)(SB + 8192);
    float* cPA  = (float*)(SB + 10240);
    float* cDAo = (float*)(SB + 12288);
    __shared__ bool amLast;

    const int blk = blockIdx.x;
    const int p = blk >> 2;
    const int s = blk & 3;
    const float* __restrict__ X = x + ((size_t)p * SZ + (size_t)s * SLAB) * SZ;

    const int tid  = threadIdx.x;
    const int w    = tid >> 5;
    const int lane = tid & 31;
    const int wr = w >> 2, wc = w & 3;
    const int c0  = wc * 128;
    const int lr0 = wr * 32;
    const bool mainRole = (wc == s);
    const bool antiRole = (wc == 3 - s);

    const float* src0 = X + (size_t)lr0 * SZ + c0 + lane * 4;   // +row*SZ per row
    const uint32_t stg = (uint32_t)__cvta_generic_to_shared(SB) + w * STG_WARP + lane * 16;
    const char* stbase = SB + w * STG_WARP + lane * 16;

    // prologue: 3 stages in flight
#pragma unroll
    for (int st = 0; st < 3; ++st) {
#pragma unroll
        for (int u = 0; u < 4; ++u)
            cpasync16(stg + st * STAGE_B + u * 512, src0 + (size_t)(st * 4 + u) * SZ);
        CP_COMMIT();
    }

    uint64_t acc01 = 0ull, acc23 = 0ull;

#pragma unroll
    for (int g = 0; g < 8; ++g) {
        if (g < 6)      { CP_WAIT(2); }
        else if (g == 6){ CP_WAIT(1); }
        else            { CP_WAIT(0); }

        const char* stp = stbase + (g % 3) * STAGE_B;
        float4 v0 = *(const float4*)(stp);
        float4 v1 = *(const float4*)(stp + 512);
        float4 v2 = *(const float4*)(stp + 1024);
        float4 v3 = *(const float4*)(stp + 1536);

        const int lrg = lr0 + 4 * g;

        float s0, s1, s2, s3;
        {
            uint64_t h0 = addf32x2(pack2(v0.x, v0.y), pack2(v0.z, v0.w));
            uint64_t h1 = addf32x2(pack2(v1.x, v1.y), pack2(v1.z, v1.w));
            uint64_t h2 = addf32x2(pack2(v2.x, v2.y), pack2(v2.z, v2.w));
            uint64_t h3 = addf32x2(pack2(v3.x, v3.y), pack2(v3.z, v3.w));
            float lo, hi;
            unpack2(h0, lo, hi); s0 = lo + hi;
            unpack2(h1, lo, hi); s1 = lo + hi;
            unpack2(h2, lo, hi); s2 = lo + hi;
            unpack2(h3, lo, hi); s3 = lo + hi;
        }

        // cut-element scalars (v-dependent, extracted early)
        float pm0 = 0.f, pm1 = 0.f, pm2 = 0.f;
        if (mainRole) { pm0 = v0.x; pm1 = v1.x + v1.y; pm2 = (v2.x + v2.y) + v2.z; }
        float pa1 = 0.f, pa2 = 0.f, pa3 = 0.f;
        if (antiRole) { pa1 = (v1.x + v1.y) + v1.z; pa2 = v2.x + v2.y; pa3 = v3.x; }

        // snapshots (strict col prefixes; acc BEFORE this group's update + corrections)
        if (mainRole) {
            const int ls = 8 * wr + g;
            if (lane == ls) {
                float lo, hi;
                unpack2(acc01, lo, hi);
                sSnapM[lrg + 0] = lo;
                sSnapM[lrg + 1] = hi + v0.y;
                unpack2(acc23, lo, hi);
                sSnapM[lrg + 2] = lo + v0.z + v1.z;
                sSnapM[lrg + 3] = hi + v0.w + v1.w + v2.w;
            }
        }
        if (antiRole) {
            const int ls = 31 - 8 * wr - g;
            if (lane == ls) {
                float lo, hi;
                unpack2(acc23, lo, hi);
                sSnapA[127 - (lrg + 0)] = hi;
                sSnapA[127 - (lrg + 1)] = lo + v0.z;
                unpack2(acc01, lo, hi);
                sSnapA[127 - (lrg + 2)] = hi + v0.y + v1.y;
                sSnapA[127 - (lrg + 3)] = lo + v0.x + v1.x + v2.x;
                sDA[lrg + 0] = v0.w;
                sDA[lrg + 1] = v1.z;
                sDA[lrg + 2] = v2.y;
                sDA[lrg + 3] = v3.x;
            }
        }

        // packed column-accumulator update (row order preserved per component)
        acc01 = addf32x2(acc01, addf32x2(addf32x2(pack2(v0.x, v0.y), pack2(v1.x, v1.y)),
                                         addf32x2(pack2(v2.x, v2.y), pack2(v3.x, v3.y))));
        acc23 = addf32x2(acc23, addf32x2(addf32x2(pack2(v0.z, v0.w), pack2(v1.z, v1.w)),
                                         addf32x2(pack2(v2.z, v2.w), pack2(v3.z, v3.w))));

        // ---- v fully consumed: refill this stage with group g+3 ----
        if (g < 5) {
#pragma unroll
            for (int u = 0; u < 4; ++u)
                cpasync16(stg + (g % 3) * STAGE_B + u * 512,
                          src0 + (size_t)((g + 3) * 4 + u) * SZ);
            CP_COMMIT();
        }

        // ---- long shuffle chains (cp.async traffic flows underneath) ----
        const float r4 = multireduce4(s0, s1, s2, s3, lane);
        if (lane < 4) sBandRow[wc * SLAB + lrg + lane] = r4;

        if (mainRole) {
            const int ls = 8 * wr + g;
            const bool lt = lane < ls, eq = lane == ls;
            float m0 = lt ? s0 : eq ? pm0 : 0.f;
            float m1 = lt ? s1 : eq ? pm1 : 0.f;
            float m2 = lt ? s2 : eq ? pm2 : 0.f;
            float m3 = (lt | eq) ? s3 : 0.f;
            const float mc = multireduce4(m0, m1, m2, m3, lane);
            if (lane < 4) sCutM[lrg + lane] = mc;
        }
        if (antiRole) {
            const int ls = 31 - 8 * wr - g;
            const bool lt = lane < ls, eq = lane == ls;
            float m0 = (lt | eq) ? s0 : 0.f;
            float m1 = lt ? s1 : eq ? pa1 : 0.f;
            float m2 = lt ? s2 : eq ? pa2 : 0.f;
            float m3 = lt ? s3 : eq ? pa3 : 0.f;
            const float mc = multireduce4(m0, m1, m2, m3, lane);
            if (lane < 4) sCutA[lrg + lane] = mc;
        }
    }

    {
        float a0, a1, a2, a3;
        unpack2(acc01, a0, a1);
        unpack2(acc23, a2, a3);
        *reinterpret_cast<float4*>(sColPart + wr * SZ + c0 + lane * 4) = make_float4(a0, a1, a2, a3);
    }
    __syncthreads();

    // ---- slab combine: columns ----
    {
        const int c = tid;
        const float q0 = sColPart[0 * SZ + c], q1 = sColPart[1 * SZ + c],
                    q2 = sColPart[2 * SZ + c], q3 = sColPart[3 * SZ + c];
        g_colsum[p][s][c] = (q0 + q1) + (q2 + q3);

        const int band = c >> 7;
        if (band == s) {
            const int lr = c - 128 * s;
            const int rg = lr >> 5;
            float sn = sSnapM[lr];
            if (rg > 0) sn += q0;
            if (rg > 1) sn += q1;
            if (rg > 2) sn += q2;
            g_snapM[p][c] = sn;
        }
        if (band == 3 - s) {
            const int la = c - 128 * (3 - s);   // == 127 - lr
            const int rg = (127 - la) >> 5;
            float sn = sSnapA[la];
            if (rg > 0) sn += q0;
            if (rg > 1) sn += q1;
            if (rg > 2) sn += q2;
            g_snapA[p][c] = sn;
        }
    }
    // ---- slab combine: rows ----
    if (tid < SLAB) {
        const int lr = tid;
        const int gr = 128 * s + lr;
        const float b0 = sBandRow[0 * SLAB + lr], b1 = sBandRow[1 * SLAB + lr],
                    b2 = sBandRow[2 * SLAB + lr], b3 = sBandRow[3 * SLAB + lr];
        g_RT[p][gr] = (b0 + b1) + (b2 + b3);

        float pm = sCutM[lr];
        if (s > 0) pm += b0;
        if (s > 1) pm += b1;
        if (s > 2) pm += b2;
        g_PM[p][gr] = pm;

        const int ab = 3 - s;
        float pa = sCutA[lr];
        if (ab > 0) pa += b0;
        if (ab > 1) pa += b1;
        if (ab > 2) pa += b2;
        g_PA[p][gr] = pa;

        g_DA[p][gr] = sDA[lr];
    }

    // ---- last-block-per-plane fused combine ----
    __threadfence();
    __syncthreads();
    if (tid == 0) {
        const unsigned t = atomicAdd(&g_cnt[p], 1u);
        amLast = (t == 3u);
        if (amLast) g_cnt[p] = 0;
    }
    __syncthreads();
    if (!amLast) return;

    {
        const int i = tid;
        const float q0 = g_colsum[p][0][i], q1 = g_colsum[p][1][i],
                    q2 = g_colsum[p][2][i], q3 = g_colsum[p][3][i];
        cCT[i] = (q0 + q1) + (q2 + q3);

        const int jm = i >> 7;
        float a1 = g_snapM[p][i];
        if (jm > 0) a1 += q0;
        if (jm > 1) a1 += q1;
        if (jm > 2) a1 += q2;
        cA1[i] = a1;

        const int ja = (SZ - 1 - i) >> 7;
        float a2 = g_snapA[p][i];
        if (ja > 0) a2 += q0;
        if (ja > 1) a2 += q1;
        if (ja > 2) a2 += q2;
        cA2[i] = a2;

        cRT[i] = g_RT[p][i]; cPM[i] = g_PM[p][i]; cPA[i] = g_PA[p][i]; cDAo[i] = g_DA[p][i];
    }
    __syncthreads();
    {
        const int i = tid;
        const int m = SZ - 1 - i;

        const float tl = cPM[i] + cA1[i];
        const float tr = cRT[i] - cPA[i] + cDAo[i] + cA2[m];
        const float bl = cPA[m] + cCT[i] - cA2[i] - cDAo[m];
        const float br = cRT[m] - cPM[m] + cCT[m] - cA1[m];

        const float inv = 1.0f / (float)(2 * i + 1);
        const int b  = p >> 3;
        const int ch = p & 7;
        float* __restrict__ o = out + ((size_t)(b * SZ + i)) * 32 + ch;
        o[0]  = tl * inv;
        o[8]  = tr * inv;
        o[16] = bl * inv;
        o[24] = br * inv;
    }
}

extern "C" void kernel_launch(void* const* d_in, const int* in_sizes, int n_in,
                              void* d_out, int out_size) {
    const float* x = (const float*)d_in[0];
    float* out = (float*)d_out;
    const int planes = in_sizes[0] / (SZ * SZ);   // 256
    static bool attrSet = false;
    if (!attrSet) {
        cudaFuncSetAttribute(slab_kernel, cudaFuncAttributeMaxDynamicSharedMemorySize, SMEM_TOTAL);
        attrSet = true;
    }
    slab_kernel<<<planes * 4, 512, SMEM_TOTAL>>>(x, out);
}

// round 12
// speedup vs baseline: 1.0641x; 1.0641x over previous
#include <cuda_runtime.h>
#include <cstdint>

#define SZ 512
#define SLAB 128
#define NPLANES 256

// cross-block scratch (allocation-free: __device__ globals)
__device__ float g_colsum[NPLANES][4][SZ];
__device__ float g_snapM[NPLANES][SZ];
__device__ float g_snapA[NPLANES][SZ];
__device__ float g_RT[NPLANES][SZ];
__device__ float g_PM[NPLANES][SZ];
__device__ float g_PA[NPLANES][SZ];
__device__ float g_DA[NPLANES][SZ];
__device__ unsigned int g_cnt[NPLANES];   // zero-init; self-reset each launch

__device__ __forceinline__ uint64_t pack2(float lo, float hi) {
    uint64_t d; asm("mov.b64 %0, {%1, %2};" : "=l"(d) : "f"(lo), "f"(hi)); return d;
}
__device__ __forceinline__ void unpack2(uint64_t d, float& lo, float& hi) {
    asm("mov.b64 {%0, %1}, %2;" : "=f"(lo), "=f"(hi) : "l"(d));
}
__device__ __forceinline__ uint64_t addf32x2(uint64_t a, uint64_t b) {
    uint64_t d; asm("add.rn.f32x2 %0, %1, %2;" : "=l"(d) : "l"(a), "l"(b)); return d;
}

// Reduce 8 independent per-lane values over the warp in 9 shuffles.
// Lane L ends holding the full 32-lane sum of value (L & 7).
__device__ __forceinline__ float multireduce8(const float* v, int lane) {
    const unsigned F = 0xffffffffu;
    const bool b0 = lane & 1;
    float x01 = (b0 ? v[1] : v[0]) + __shfl_xor_sync(F, b0 ? v[0] : v[1], 1);
    float x23 = (b0 ? v[3] : v[2]) + __shfl_xor_sync(F, b0 ? v[2] : v[3], 1);
    float x45 = (b0 ? v[5] : v[4]) + __shfl_xor_sync(F, b0 ? v[4] : v[5], 1);
    float x67 = (b0 ? v[7] : v[6]) + __shfl_xor_sync(F, b0 ? v[6] : v[7], 1);
    const bool b1 = lane & 2;
    float y03 = (b1 ? x23 : x01) + __shfl_xor_sync(F, b1 ? x01 : x23, 2);
    float y47 = (b1 ? x67 : x45) + __shfl_xor_sync(F, b1 ? x45 : x67, 2);
    const bool b2 = lane & 4;
    float z = (b2 ? y47 : y03) + __shfl_xor_sync(F, b2 ? y03 : y47, 4);
    z += __shfl_xor_sync(F, z, 8);
    z += __shfl_xor_sync(F, z, 16);
    return z;
}

// Reduce 16 independent per-lane values over the warp in 16 shuffles (ONE chain).
// Lane L ends holding the full 32-lane sum of value (L & 15).
__device__ __forceinline__ float multireduce16(const float* a, int lane) {
    const unsigned F = 0xffffffffu;
    const bool b0 = lane & 1;
    float t0 = (b0 ? a[1]  : a[0])  + __shfl_xor_sync(F, b0 ? a[0]  : a[1],  1);
    float t1 = (b0 ? a[3]  : a[2])  + __shfl_xor_sync(F, b0 ? a[2]  : a[3],  1);
    float t2 = (b0 ? a[5]  : a[4])  + __shfl_xor_sync(F, b0 ? a[4]  : a[5],  1);
    float t3 = (b0 ? a[7]  : a[6])  + __shfl_xor_sync(F, b0 ? a[6]  : a[7],  1);
    float t4 = (b0 ? a[9]  : a[8])  + __shfl_xor_sync(F, b0 ? a[8]  : a[9],  1);
    float t5 = (b0 ? a[11] : a[10]) + __shfl_xor_sync(F, b0 ? a[10] : a[11], 1);
    float t6 = (b0 ? a[13] : a[12]) + __shfl_xor_sync(F, b0 ? a[12] : a[13], 1);
    float t7 = (b0 ? a[15] : a[14]) + __shfl_xor_sync(F, b0 ? a[14] : a[15], 1);
    const bool b1 = lane & 2;
    float u0 = (b1 ? t1 : t0) + __shfl_xor_sync(F, b1 ? t0 : t1, 2);
    float u1 = (b1 ? t3 : t2) + __shfl_xor_sync(F, b1 ? t2 : t3, 2);
    float u2 = (b1 ? t5 : t4) + __shfl_xor_sync(F, b1 ? t4 : t5, 2);
    float u3 = (b1 ? t7 : t6) + __shfl_xor_sync(F, b1 ? t6 : t7, 2);
    const bool b2 = lane & 4;
    float w0 = (b2 ? u1 : u0) + __shfl_xor_sync(F, b2 ? u0 : u1, 4);
    float w1 = (b2 ? u3 : u2) + __shfl_xor_sync(F, b2 ? u2 : u3, 4);
    const bool b3 = lane & 8;
    float z = (b3 ? w1 : w0) + __shfl_xor_sync(F, b3 ? w0 : w1, 8);
    z += __shfl_xor_sync(F, z, 16);
    return z;
}

__global__ __launch_bounds__(512, 2)
void slab_kernel(const float* __restrict__ x, float* __restrict__ out) {
    __shared__ float sBandRow[4][SLAB];
    __shared__ float sColPart[4][SZ];
    __shared__ float sCutM[SLAB];
    __shared__ float sCutA[SLAB];
    __shared__ float sSnapM[SLAB];
    __shared__ float sSnapA[SLAB];
    __shared__ float sDA[SLAB];
    __shared__ float cA1[SZ], cA2[SZ], cCT[SZ], cRT[SZ], cPM[SZ], cPA[SZ], cDAo[SZ];
    __shared__ bool amLast;

    const int blk = blockIdx.x;
    const int p = blk >> 2;
    const int s = blk & 3;
    const float* __restrict__ X = x + ((size_t)p * SZ + (size_t)s * SLAB) * SZ;

    const int tid  = threadIdx.x;
    const int w    = tid >> 5;
    const int lane = tid & 31;
    const int wr = w >> 2, wc = w & 3;
    const int c0  = wc * 128;
    const int lr0 = wr * 32;
    const bool mainRole = (wc == s);
    const bool antiRole = (wc == 3 - s);

    const float4* __restrict__ base =
        reinterpret_cast<const float4*>(X + (size_t)lr0 * SZ + c0) + lane;
    const int RS4 = SZ / 4;

    uint64_t acc01 = 0ull, acc23 = 0ull;

#pragma unroll
    for (int g = 0; g < 4; ++g) {
        const int lrg = lr0 + 8 * g;

        float4 v[8];
#pragma unroll
        for (int u = 0; u < 8; u++)
            v[u] = __ldcs(base + (8 * g + u) * RS4);

        float a16[16];               // [0..7]=row partials, [8..15]=masked cut partials
#pragma unroll
        for (int u = 0; u < 8; u++) {
            uint64_t h = addf32x2(pack2(v[u].x, v[u].y), pack2(v[u].z, v[u].w));
            float lo, hi; unpack2(h, lo, hi);
            a16[u] = lo + hi;
        }
        const float* sv = a16;

        if (mainRole) {
            const int ls0 = 8 * wr + 2 * g;
            const int ls1 = ls0 + 1;
            {
                const bool lt = lane < ls0, eq = lane == ls0;
                a16[8]  = lt ? sv[0] : eq ? v[0].x : 0.f;
                a16[9]  = lt ? sv[1] : eq ? (v[1].x + v[1].y) : 0.f;
                a16[10] = lt ? sv[2] : eq ? ((v[2].x + v[2].y) + v[2].z) : 0.f;
                a16[11] = (lt | eq) ? sv[3] : 0.f;
            }
            {
                const bool lt = lane < ls1, eq = lane == ls1;
                a16[12] = lt ? sv[4] : eq ? v[4].x : 0.f;
                a16[13] = lt ? sv[5] : eq ? (v[5].x + v[5].y) : 0.f;
                a16[14] = lt ? sv[6] : eq ? ((v[6].x + v[6].y) + v[6].z) : 0.f;
                a16[15] = (lt | eq) ? sv[7] : 0.f;
            }
            const float r16 = multireduce16(a16, lane);
            if (lane < 8)                   sBandRow[wc][lrg + lane] = r16;
            else if (lane < 16)             sCutM[lrg + (lane - 8)]  = r16;
        } else if (antiRole) {
            const int lsA0 = (127 - lrg) >> 2;
            const int lsA1 = lsA0 - 1;
            {
                const bool lt = lane < lsA0, eq = lane == lsA0;
                a16[8]  = (lt | eq) ? sv[0] : 0.f;
                a16[9]  = lt ? sv[1] : eq ? ((v[1].x + v[1].y) + v[1].z) : 0.f;
                a16[10] = lt ? sv[2] : eq ? (v[2].x + v[2].y) : 0.f;
                a16[11] = lt ? sv[3] : eq ? v[3].x : 0.f;
            }
            {
                const bool lt = lane < lsA1, eq = lane == lsA1;
                a16[12] = (lt | eq) ? sv[4] : 0.f;
                a16[13] = lt ? sv[5] : eq ? ((v[5].x + v[5].y) + v[5].z) : 0.f;
                a16[14] = lt ? sv[6] : eq ? (v[6].x + v[6].y) : 0.f;
                a16[15] = lt ? sv[7] : eq ? v[7].x : 0.f;
            }
            const float r16 = multireduce16(a16, lane);
            if (lane < 8)                   sBandRow[wc][lrg + lane] = r16;
            else if (lane < 16)             sCutA[lrg + (lane - 8)]  = r16;
        } else {
            const float r8 = multireduce8(sv, lane);
            if (lane < 8) sBandRow[wc][lrg + lane] = r8;
        }

        // snapshots (strict col prefixes, read acc BEFORE update) + packed acc update
#pragma unroll
        for (int u = 0; u < 8; u++) {
            const int lr = lrg + u;
            if (mainRole) {
                const int ls = 8 * wr + 2 * g + (u >> 2);
                if (lane == ls) {
                    float lo, hi, sn;
                    if ((u & 3) < 2) { unpack2(acc01, lo, hi); sn = ((u & 3) == 0) ? lo : hi; }
                    else             { unpack2(acc23, lo, hi); sn = ((u & 3) == 2) ? lo : hi; }
                    sSnapM[lr] = sn;
                }
            }
            if (antiRole) {
                const int lsA = ((127 - lrg) >> 2) - (u >> 2);
                const int kA = 3 - (u & 3);
                if (lane == lsA) {
                    const float e = (kA == 0) ? v[u].x : (kA == 1) ? v[u].y
                                  : (kA == 2) ? v[u].z : v[u].w;
                    float lo, hi, sn;
                    if (kA < 2) { unpack2(acc01, lo, hi); sn = (kA == 0) ? lo : hi; }
                    else        { unpack2(acc23, lo, hi); sn = (kA == 2) ? lo : hi; }
                    sSnapA[127 - lr] = sn;
                    sDA[lr] = e;
                }
            }
            acc01 = addf32x2(acc01, pack2(v[u].x, v[u].y));
            acc23 = addf32x2(acc23, pack2(v[u].z, v[u].w));
        }
    }

    {
        float a0, a1, a2, a3;
        unpack2(acc01, a0, a1);
        unpack2(acc23, a2, a3);
        reinterpret_cast<float4*>(&sColPart[wr][c0])[lane] = make_float4(a0, a1, a2, a3);
    }
    __syncthreads();

    // ---- slab combine: columns ----
    {
        const int c = tid;
        const float q0 = sColPart[0][c], q1 = sColPart[1][c],
                    q2 = sColPart[2][c], q3 = sColPart[3][c];
        g_colsum[p][s][c] = (q0 + q1) + (q2 + q3);

        const int band = c >> 7;
        if (band == s) {
            const int lr = c - 128 * s;
            const int rg = lr >> 5;
            float sn = sSnapM[lr];
            if (rg > 0) sn += q0;
            if (rg > 1) sn += q1;
            if (rg > 2) sn += q2;
            g_snapM[p][c] = sn;
        }
        if (band == 3 - s) {
            const int la = c - 128 * (3 - s);   // == 127 - lr
            const int rg = (127 - la) >> 5;
            float sn = sSnapA[la];
            if (rg > 0) sn += q0;
            if (rg > 1) sn += q1;
            if (rg > 2) sn += q2;
            g_snapA[p][c] = sn;
        }
    }
    // ---- slab combine: rows ----
    if (tid < SLAB) {
        const int lr = tid;
        const int gr = 128 * s + lr;
        const float b0 = sBandRow[0][lr], b1 = sBandRow[1][lr],
                    b2 = sBandRow[2][lr], b3 = sBandRow[3][lr];
        g_RT[p][gr] = (b0 + b1) + (b2 + b3);

        float pm = sCutM[lr];
        if (s > 0) pm += b0;
        if (s > 1) pm += b1;
        if (s > 2) pm += b2;
        g_PM[p][gr] = pm;

        const int ab = 3 - s;
        float pa = sCutA[lr];
        if (ab > 0) pa += b0;
        if (ab > 1) pa += b1;
        if (ab > 2) pa += b2;
        g_PA[p][gr] = pa;

        g_DA[p][gr] = sDA[lr];
    }

    // ---- last-block-per-plane fused combine ----
    __threadfence();
    __syncthreads();
    if (tid == 0) {
        const unsigned t = atomicAdd(&g_cnt[p], 1u);
        amLast = (t == 3u);
        if (amLast) g_cnt[p] = 0;
    }
    __syncthreads();
    if (!amLast) return;

    {
        const int i = tid;
        const float q0 = g_colsum[p][0][i], q1 = g_colsum[p][1][i],
                    q2 = g_colsum[p][2][i], q3 = g_colsum[p][3][i];
        cCT[i] = (q0 + q1) + (q2 + q3);

        const int jm = i >> 7;
        float a1 = g_snapM[p][i];
        if (jm > 0) a1 += q0;
        if (jm > 1) a1 += q1;
        if (jm > 2) a1 += q2;
        cA1[i] = a1;

        const int ja = (SZ - 1 - i) >> 7;
        float a2 = g_snapA[p][i];
        if (ja > 0) a2 += q0;
        if (ja > 1) a2 += q1;
        if (ja > 2) a2 += q2;
        cA2[i] = a2;

        cRT[i] = g_RT[p][i]; cPM[i] = g_PM[p][i]; cPA[i] = g_PA[p][i]; cDAo[i] = g_DA[p][i];
    }
    __syncthreads();
    {
        const int i = tid;
        const int m = SZ - 1 - i;

        const float tl = cPM[i] + cA1[i];
        const float tr = cRT[i] - cPA[i] + cDAo[i] + cA2[m];
        const float bl = cPA[m] + cCT[i] - cA2[i] - cDAo[m];
        const float br = cRT[m] - cPM[m] + cCT[m] - cA1[m];

        const float inv = 1.0f / (float)(2 * i + 1);
        const int b  = p >> 3;
        const int ch = p & 7;
        float* __restrict__ o = out + ((size_t)(b * SZ + i)) * 32 + ch;
        o[0]  = tl * inv;
        o[8]  = tr * inv;
        o[16] = bl * inv;
        o[24] = br * inv;
    }
}

extern "C" void kernel_launch(void* const* d_in, const int* in_sizes, int n_in,
                              void* d_out, int out_size) {
    const float* x = (const float*)d_in[0];
    float* out = (float*)d_out;
    const int planes = in_sizes[0] / (SZ * SZ);   // 256
    slab_kernel<<<planes * 4, 512>>>(x, out);
}

// round 13
// speedup vs baseline: 1.1047x; 1.0382x over previous
#include <cuda_runtime.h>
#include <cstdint>

#define SZ 512
#define SLAB 128
#define NPLANES 256

// dynamic smem layout (bytes)
#define OFF_ROWP 0                     // float[4][128][33] row partials
#define OFF_COLP 67584                 // float[4][512]
#define OFF_PKM  75776                 // float[128]
#define OFF_PKA  76288                 // float[128]
#define OFF_SNM  76800                 // float[128]
#define OFF_SNA  77312                 // float[128]
#define OFF_DAE  77824                 // float[128]
#define OFF_BAND 78336                 // float[4][128]
#define OFF_CUTM 80384                 // float[128]
#define OFF_CUTA 80896                 // float[128]
#define SMEM_TOTAL 81408

// cross-block scratch (allocation-free: __device__ globals)
__device__ float g_colsum[NPLANES][4][SZ];
__device__ float g_snapM[NPLANES][SZ];
__device__ float g_snapA[NPLANES][SZ];
__device__ float g_RT[NPLANES][SZ];
__device__ float g_PM[NPLANES][SZ];
__device__ float g_PA[NPLANES][SZ];
__device__ float g_DA[NPLANES][SZ];
__device__ unsigned int g_cnt[NPLANES];   // zero-init; self-reset each launch

__device__ __forceinline__ uint64_t pack2(float lo, float hi) {
    uint64_t d; asm("mov.b64 %0, {%1, %2};" : "=l"(d) : "f"(lo), "f"(hi)); return d;
}
__device__ __forceinline__ void unpack2(uint64_t d, float& lo, float& hi) {
    asm("mov.b64 {%0, %1}, %2;" : "=f"(lo), "=f"(hi) : "l"(d));
}
__device__ __forceinline__ uint64_t addf32x2(uint64_t a, uint64_t b) {
    uint64_t d; asm("add.rn.f32x2 %0, %1, %2;" : "=l"(d) : "l"(a), "l"(b)); return d;
}

__global__ __launch_bounds__(512, 2)
void slab_kernel(const float* __restrict__ x, float* __restrict__ out) {
    extern __shared__ char SB[];
    float* sRowPart = (float*)(SB + OFF_ROWP);   // [(band*128+row)*33 + lane]
    float* sColPart = (float*)(SB + OFF_COLP);   // [rowgroup*512 + col]
    float* sPkM     = (float*)(SB + OFF_PKM);
    float* sPkA     = (float*)(SB + OFF_PKA);
    float* sSnapM   = (float*)(SB + OFF_SNM);
    float* sSnapA   = (float*)(SB + OFF_SNA);
    float* sDA      = (float*)(SB + OFF_DAE);
    float* sBandRow = (float*)(SB + OFF_BAND);   // [band*128 + row]
    float* sCutM    = (float*)(SB + OFF_CUTM);
    float* sCutA    = (float*)(SB + OFF_CUTA);
    // last-block combine arrays alias the (dead-by-then) sRowPart region
    float* cA1  = (float*)(SB + 0);
    float* cA2  = (float*)(SB + 2048);
    float* cCT  = (float*)(SB + 4096);
    float* cRT  = (float*)(SB + 6144);
    float* cPM  = (float*)(SB + 8192);
    float* cPA  = (float*)(SB + 10240);
    float* cDAo = (float*)(SB + 12288);
    __shared__ bool amLast;

    const int blk = blockIdx.x;
    const int p = blk >> 2;
    const int s = blk & 3;
    const float* __restrict__ X = x + ((size_t)p * SZ + (size_t)s * SLAB) * SZ;

    const int tid  = threadIdx.x;
    const int w    = tid >> 5;
    const int lane = tid & 31;
    const int wr = w >> 2, wc = w & 3;
    const int c0  = wc * 128;
    const int lr0 = wr * 32;
    const bool mainRole = (wc == s);
    const bool antiRole = (wc == 3 - s);

    const float4* __restrict__ base =
        reinterpret_cast<const float4*>(X + (size_t)lr0 * SZ + c0) + lane;
    const int RS4 = SZ / 4;

    uint64_t acc01 = 0ull, acc23 = 0ull;

#pragma unroll
    for (int g = 0; g < 4; ++g) {
        const int lrg = lr0 + 8 * g;

        float4 v[8];
#pragma unroll
        for (int u = 0; u < 8; u++)
            v[u] = __ldcs(base + (8 * g + u) * RS4);

        float sv[8];
#pragma unroll
        for (int u = 0; u < 8; u++) {
            uint64_t h = addf32x2(pack2(v[u].x, v[u].y), pack2(v[u].z, v[u].w));
            float lo, hi; unpack2(h, lo, hi);
            sv[u] = lo + hi;
        }

        // store per-lane row partials (conflict-free: consecutive lanes -> consecutive banks)
        {
            float* rp = sRowPart + (wc * 128 + lrg) * 33 + lane;
#pragma unroll
            for (int u = 0; u < 8; u++)
                rp[u * 33] = sv[u];
        }

        // role-warp scalars: cut pk, snapshots (acc read BEFORE that row's update) + acc update
#pragma unroll
        for (int u = 0; u < 8; u++) {
            const int lr = lrg + u;
            if (mainRole) {
                const int ls = 8 * wr + 2 * g + (u >> 2);
                const int k = u & 3;                   // compile-time
                if (lane == ls) {
                    const float pkv = (k == 0) ? v[u].x
                                    : (k == 1) ? (v[u].x + v[u].y)
                                    : (k == 2) ? ((v[u].x + v[u].y) + v[u].z)
                                    : sv[u];
                    sPkM[lr] = pkv;
                    float lo, hi, sn;
                    if (k < 2) { unpack2(acc01, lo, hi); sn = (k == 0) ? lo : hi; }
                    else       { unpack2(acc23, lo, hi); sn = (k == 2) ? lo : hi; }
                    sSnapM[lr] = sn;
                }
            }
            if (antiRole) {
                const int lsA = ((127 - lrg) >> 2) - (u >> 2);
                const int kA = 3 - (u & 3);            // compile-time
                if (lane == lsA) {
                    const float pkv = (kA == 3) ? sv[u]
                                    : (kA == 2) ? ((v[u].x + v[u].y) + v[u].z)
                                    : (kA == 1) ? (v[u].x + v[u].y)
                                    : v[u].x;
                    sPkA[lr] = pkv;
                    const float e = (kA == 0) ? v[u].x : (kA == 1) ? v[u].y
                                  : (kA == 2) ? v[u].z : v[u].w;
                    float lo, hi, sn;
                    if (kA < 2) { unpack2(acc01, lo, hi); sn = (kA == 0) ? lo : hi; }
                    else        { unpack2(acc23, lo, hi); sn = (kA == 2) ? lo : hi; }
                    sSnapA[127 - lr] = sn;
                    sDA[lr] = e;
                }
            }
            acc01 = addf32x2(acc01, pack2(v[u].x, v[u].y));
            acc23 = addf32x2(acc23, pack2(v[u].z, v[u].w));
        }
    }

    {
        float a0, a1, a2, a3;
        unpack2(acc01, a0, a1);
        unpack2(acc23, a2, a3);
        *reinterpret_cast<float4*>(sColPart + wr * SZ + c0 + lane * 4) = make_float4(a0, a1, a2, a3);
    }
    __syncthreads();

    // ---- phase 2a: reduce row partials from smem (no shuffles) ----
    {
        const int band = tid >> 7;
        const int lr = tid & 127;
        const float* rp = sRowPart + (band * 128 + lr) * 33;
        const int lsM = lr >> 2;
        const int lsA = (127 - lr) >> 2;
        float full = 0.f, cutM = 0.f, cutA = 0.f;
#pragma unroll
        for (int k = 0; k < 32; ++k) {
            const float vv = rp[k];
            full += vv;
            if (k < lsM) cutM += vv;
            if (k < lsA) cutA += vv;
        }
        sBandRow[band * 128 + lr] = full;
        if (band == s)     sCutM[lr] = cutM + sPkM[lr];
        if (band == 3 - s) sCutA[lr] = cutA + sPkA[lr];
    }
    // ---- slab combine: columns (independent of phase 2a) ----
    {
        const int c = tid;
        const float q0 = sColPart[0 * SZ + c], q1 = sColPart[1 * SZ + c],
                    q2 = sColPart[2 * SZ + c], q3 = sColPart[3 * SZ + c];
        g_colsum[p][s][c] = (q0 + q1) + (q2 + q3);

        const int band = c >> 7;
        if (band == s) {
            const int lr = c - 128 * s;
            const int rg = lr >> 5;
            float sn = sSnapM[lr];
            if (rg > 0) sn += q0;
            if (rg > 1) sn += q1;
            if (rg > 2) sn += q2;
            g_snapM[p][c] = sn;
        }
        if (band == 3 - s) {
            const int la = c - 128 * (3 - s);   // == 127 - lr
            const int rg = (127 - la) >> 5;
            float sn = sSnapA[la];
            if (rg > 0) sn += q0;
            if (rg > 1) sn += q1;
            if (rg > 2) sn += q2;
            g_snapA[p][c] = sn;
        }
    }
    __syncthreads();

    // ---- slab combine: rows ----
    if (tid < SLAB) {
        const int lr = tid;
        const int gr = 128 * s + lr;
        const float b0 = sBandRow[0 * 128 + lr], b1 = sBandRow[1 * 128 + lr],
                    b2 = sBandRow[2 * 128 + lr], b3 = sBandRow[3 * 128 + lr];
        g_RT[p][gr] = (b0 + b1) + (b2 + b3);

        float pm = sCutM[lr];
        if (s > 0) pm += b0;
        if (s > 1) pm += b1;
        if (s > 2) pm += b2;
        g_PM[p][gr] = pm;

        const int ab = 3 - s;
        float pa = sCutA[lr];
        if (ab > 0) pa += b0;
        if (ab > 1) pa += b1;
        if (ab > 2) pa += b2;
        g_PA[p][gr] = pa;

        g_DA[p][gr] = sDA[lr];
    }

    // ---- last-block-per-plane fused combine ----
    __threadfence();
    __syncthreads();
    if (tid == 0) {
        const unsigned t = atomicAdd(&g_cnt[p], 1u);
        amLast = (t == 3u);
        if (amLast) g_cnt[p] = 0;
    }
    __syncthreads();
    if (!amLast) return;

    {
        const int i = tid;
        const float q0 = g_colsum[p][0][i], q1 = g_colsum[p][1][i],
                    q2 = g_colsum[p][2][i], q3 = g_colsum[p][3][i];
        cCT[i] = (q0 + q1) + (q2 + q3);

        const int jm = i >> 7;
        float a1 = g_snapM[p][i];
        if (jm > 0) a1 += q0;
        if (jm > 1) a1 += q1;
        if (jm > 2) a1 += q2;
        cA1[i] = a1;

        const int ja = (SZ - 1 - i) >> 7;
        float a2 = g_snapA[p][i];
        if (ja > 0) a2 += q0;
        if (ja > 1) a2 += q1;
        if (ja > 2) a2 += q2;
        cA2[i] = a2;

        cRT[i] = g_RT[p][i]; cPM[i] = g_PM[p][i]; cPA[i] = g_PA[p][i]; cDAo[i] = g_DA[p][i];
    }
    __syncthreads();
    {
        const int i = tid;
        const int m = SZ - 1 - i;

        const float tl = cPM[i] + cA1[i];
        const float tr = cRT[i] - cPA[i] + cDAo[i] + cA2[m];
        const float bl = cPA[m] + cCT[i] - cA2[i] - cDAo[m];
        const float br = cRT[m] - cPM[m] + cCT[m] - cA1[m];

        const float inv = 1.0f / (float)(2 * i + 1);
        const int b  = p >> 3;
        const int ch = p & 7;
        float* __restrict__ o = out + ((size_t)(b * SZ + i)) * 32 + ch;
        o[0]  = tl * inv;
        o[8]  = tr * inv;
        o[16] = bl * inv;
        o[24] = br * inv;
    }
}

extern "C" void kernel_launch(void* const* d_in, const int* in_sizes, int n_in,
                              void* d_out, int out_size) {
    const float* x = (const float*)d_in[0];
    float* out = (float*)d_out;
    const int planes = in_sizes[0] / (SZ * SZ);   // 256
    static bool attrSet = false;
    if (!attrSet) {
        cudaFuncSetAttribute(slab_kernel, cudaFuncAttributeMaxDynamicSharedMemorySize, SMEM_TOTAL);
        attrSet = true;
    }
    slab_kernel<<<planes * 4, 512, SMEM_TOTAL>>>(x, out);
}